// round 9
// baseline (speedup 1.0000x reference)
#include <cuda_runtime.h>
#include <cuda_bf16.h>

#define SLEN 256
#define BSZ 8
#define NH 16
#define DH 64
#define IND 1024
#define ROWS (SLEN*BSZ) /* 2048 */

typedef unsigned long long ull;
typedef unsigned int uint32;

// ---- scratch (no allocs allowed -> device globals) ----
__device__ unsigned short g_ys_hi[ROWS * IND];  // scan outputs, bf16 hi (4MB)
__device__ unsigned short g_ys_lo[ROWS * IND];  // bf16 lo of residual (4MB)
__device__ unsigned short g_whi[IND * IND];     // out_w bf16 hi (2MB)
__device__ unsigned short g_wlo[IND * IND];     // out_w bf16 lo (2MB)
__device__ float g_mu[ROWS];
__device__ float g_rs[ROWS];

// ---- f32x2 helpers (sm_103a packed fp32 math, PTX-only) ----
__device__ __forceinline__ ull pack2(float lo, float hi) {
    ull r;
    asm("mov.b64 %0, {%1,%2};" : "=l"(r) : "f"(lo), "f"(hi));
    return r;
}
__device__ __forceinline__ void unpack2(ull v, float& lo, float& hi) {
    asm("mov.b64 {%0,%1}, %2;" : "=f"(lo), "=f"(hi) : "l"(v));
}
__device__ __forceinline__ ull ffma2(ull a, ull b, ull c) {
    ull d;
    asm("fma.rn.f32x2 %0, %1, %2, %3;" : "=l"(d) : "l"(a), "l"(b), "l"(c));
    return d;
}
__device__ __forceinline__ ull fmul2(ull a, ull b) {
    ull d;
    asm("mul.rn.f32x2 %0, %1, %2;" : "=l"(d) : "l"(a), "l"(b));
    return d;
}
__device__ __forceinline__ ull fadd2(ull a, ull b) {
    ull d;
    asm("add.rn.f32x2 %0, %1, %2;" : "=l"(d) : "l"(a), "l"(b));
    return d;
}
__device__ __forceinline__ float warp_sum(float v) {
    #pragma unroll
    for (int o = 16; o; o >>= 1) v += __shfl_xor_sync(0xffffffffu, v, o);
    return v;
}
// bf16 hi/lo split
__device__ __forceinline__ void split_bf16(float v, unsigned short& hi, unsigned short& lo) {
    __nv_bfloat16 hb = __float2bfloat16_rn(v);
    float rem = v - __bfloat162float(hb);
    hi = __bfloat16_as_ushort(hb);
    lo = __bfloat16_as_ushort(__float2bfloat16_rn(rem));
}
// tensor-core primitives
__device__ __forceinline__ uint32 smaddr(const void* p) {
    return (uint32)__cvta_generic_to_shared(p);
}
__device__ __forceinline__ void ldmx4(uint32* r, uint32 a) {
    asm volatile("ldmatrix.sync.aligned.m8n8.x4.shared.b16 {%0,%1,%2,%3},[%4];"
                 : "=r"(r[0]), "=r"(r[1]), "=r"(r[2]), "=r"(r[3]) : "r"(a));
}
__device__ __forceinline__ void mma16816(float* d, const uint32* a, uint32 b0, uint32 b1) {
    asm volatile(
        "mma.sync.aligned.m16n8k16.row.col.f32.bf16.bf16.f32 "
        "{%0,%1,%2,%3},{%4,%5,%6,%7},{%8,%9},{%0,%1,%2,%3};"
        : "+f"(d[0]), "+f"(d[1]), "+f"(d[2]), "+f"(d[3])
        : "r"(a[0]), "r"(a[1]), "r"(a[2]), "r"(a[3]), "r"(b0), "r"(b1));
}
// per-pair named barrier (128 threads; id 1 for pair 0, id 2 for pair 1)
__device__ __forceinline__ void pair_bar(int pl) {
    asm volatile("bar.sync %0, 128;" :: "r"(pl + 1) : "memory");
}

// ============================================================
// Kernel 0: split out_w into bf16 hi/lo
// ============================================================
__global__ __launch_bounds__(256) void wconv_kernel(const float* __restrict__ W) {
    int idx = (blockIdx.x * 256 + threadIdx.x) * 4;
    float4 v = *(const float4*)(W + idx);
    unsigned short h0, l0, h1, l1, h2, l2, h3, l3;
    split_bf16(v.x, h0, l0); split_bf16(v.y, h1, l1);
    split_bf16(v.z, h2, l2); split_bf16(v.w, h3, l3);
    uint2 hv, lv;
    hv.x = (uint32)h0 | ((uint32)h1 << 16); hv.y = (uint32)h2 | ((uint32)h3 << 16);
    lv.x = (uint32)l0 | ((uint32)l1 << 16); lv.y = (uint32)l2 | ((uint32)l3 << 16);
    *(uint2*)(g_whi + idx) = hv;
    *(uint2*)(g_wlo + idx) = lv;
}

// ============================================================
// Kernel 1: LN row stats + SRWM scan.
// TWO independent (b,head) pairs per CTA (256 threads, 64 CTAs):
// warps 0-3 = pair A, warps 4-7 = pair B, each synced by its own
// named barrier -> 2 warps/SMSP from independent recurrences
// interleave and hide each other's latency.
// Within a pair: thread p-tid t owns row r=t>>1, cols
// [(t&1)*32,+32) of Wy/Wq/Wk as 16 packed f32x2 regs each.
// Warp c owns wb[:,c]. One barrier per step; phase-A smem
// double-buffered by parity; phase B writes registers only.
// ============================================================
__global__ __launch_bounds__(256, 1) void srwm_scan_kernel(
    const float* __restrict__ h,
    const float* __restrict__ Wy0, const float* __restrict__ Wq0,
    const float* __restrict__ Wk0, const float* __restrict__ wb0)
{
    const int tid  = threadIdx.x;
    const int pl   = tid >> 7;            // pair slot in CTA: 0/1
    const int ptid = tid & 127;           // tid within pair
    const int pair = blockIdx.x * 2 + pl; // 0..127
    const int b  = pair >> 4;
    const int hd = pair & 15;
    const int r    = ptid >> 1;           // row 0..63
    const int hf   = ptid & 1;            // column half
    const int cb   = hf * 32;             // column base
    const int lane = tid & 31;
    const int warp = ptid >> 5;           // warp within pair: 0..3

    // ---------- fused LayerNorm stats: 16 rows per pair ----------
    {
        #pragma unroll
        for (int rr = 0; rr < 4; rr++) {
            int row = pair * 16 + warp * 4 + rr;
            const float* p = h + (size_t)row * IND + lane * 4;
            float s = 0.f, s2 = 0.f;
            #pragma unroll
            for (int i = 0; i < 8; i++) {
                float4 v = *(const float4*)(p + i * 128);
                s += (v.x + v.y) + (v.z + v.w);
                s2 = fmaf(v.x, v.x, s2); s2 = fmaf(v.y, v.y, s2);
                s2 = fmaf(v.z, v.z, s2); s2 = fmaf(v.w, v.w, s2);
            }
            s  = warp_sum(s);
            s2 = warp_sum(s2);
            if (lane == 0) {
                float mu  = s * (1.f / IND);
                float var = s2 * (1.f / IND) - mu * mu;
                g_mu[row] = mu;
                g_rs[row] = rsqrtf(var + 1e-5f);
            }
        }
    }

    __shared__ __align__(16) float xs[2][2][64];
    __shared__ __align__(16) float eqs[2][2][64], eks[2][2][64];
    __shared__ __align__(16) float pbp[2][2][8][4];   // [pl][p][i][c]

    // register-resident fast weights as packed f32x2 pairs (16 each)
    ull wy2[16], wq2[16], wk2[16];
    {
        const int base = hd * 4096 + r * 64 + cb;   // 16B-aligned
        const ulonglong2* py = (const ulonglong2*)(Wy0 + base);
        const ulonglong2* pq = (const ulonglong2*)(Wq0 + base);
        const ulonglong2* pk = (const ulonglong2*)(Wk0 + base);
        #pragma unroll
        for (int j = 0; j < 8; j++) {
            ulonglong2 vy = py[j]; wy2[2*j] = vy.x; wy2[2*j+1] = vy.y;
            ulonglong2 vq = pq[j]; wq2[2*j] = vq.x; wq2[2*j+1] = vq.y;
            ulonglong2 vk = pk[j]; wk2[2*j] = vk.x; wk2[2*j+1] = vk.y;
        }
    }
    // wb: global layout (hd, j=64, c=4). Warp c owns column c.
    float wbl = wb0[hd * 256 + lane * 4 + warp];
    float wbh = wb0[hd * 256 + (lane + 32) * 4 + warp];

    const float*    hp  = h       + (size_t)b * IND + hd * 64;
    unsigned short* yhp = g_ys_hi + (size_t)b * IND + hd * 64;
    unsigned short* ylp = g_ys_lo + (size_t)b * IND + hd * 64;
    const int stride = BSZ * IND;

    // preload x[0]; prefetch x[1] into regs
    if (ptid < 64) xs[pl][0][ptid] = hp[ptid];
    float nx = (ptid < 64) ? __ldg(hp + stride + ptid) : 0.f;
    pair_bar(pl);

    for (int t = 0; t < SLEN; ++t) {
        const int p  = t & 1;
        const int pn = p ^ 1;

        // ================= Phase A (reads xs[pl][p]) =================
        ull ayA = 0ull, ayB = 0ull, aqA = 0ull, aqB = 0ull, akA = 0ull, akB = 0ull;
        #pragma unroll
        for (int j = 0; j < 8; j++) {
            ull x2a = *(const ull*)&xs[pl][p][cb + 2*j];
            ull x2b = *(const ull*)&xs[pl][p][cb + 16 + 2*j];
            ayA = ffma2(wy2[j], x2a, ayA);  ayB = ffma2(wy2[j+8], x2b, ayB);
            aqA = ffma2(wq2[j], x2a, aqA);  aqB = ffma2(wq2[j+8], x2b, aqB);
            akA = ffma2(wk2[j], x2a, akA);  akB = ffma2(wk2[j+8], x2b, akB);
        }
        ull ay = fadd2(ayA, ayB), aq = fadd2(aqA, aqB), ak = fadd2(akA, akB);
        float zy, zq, zk, hi_;
        unpack2(ay, zy, hi_); zy += hi_;
        unpack2(aq, zq, hi_); zq += hi_;
        unpack2(ak, zk, hi_); zk += hi_;
        zy += __shfl_xor_sync(0xffffffffu, zy, 1);
        zq += __shfl_xor_sync(0xffffffffu, zq, 1);
        zk += __shfl_xor_sync(0xffffffffu, zk, 1);

        float eq = __expf(zq), ek = __expf(zk);
        if (hf == 0) {
            eqs[pl][p][r] = eq; eks[pl][p][r] = ek;
            unsigned short yh, yl;
            split_bf16(zy, yh, yl);
            yhp[(size_t)t * stride + r] = yh;     // y output (pre-update Wy)
            ylp[(size_t)t * stride + r] = yl;
        }
        // beta partial: 2 shfl levels; lanes 0..7 hold 8 partials
        {
            float pb = fmaf(wbl, xs[pl][p][lane], wbh * xs[pl][p][lane + 32]);
            pb += __shfl_xor_sync(0xffffffffu, pb, 16);
            pb += __shfl_xor_sync(0xffffffffu, pb, 8);
            if (lane < 8) pbp[pl][p][lane][warp] = pb;
        }
        if (ptid < 64 && t + 1 < SLEN) xs[pl][pn][ptid] = nx;  // publish x[t+1]
        pair_bar(pl);   // single per-pair barrier per step

        // ============ Phase B (reads bank p, writes regs only) ============
        if (ptid < 64 && t + 2 < SLEN) nx = __ldg(hp + (size_t)(t + 2) * stride + ptid);

        ull sqA = 0ull, sqB = 0ull, skA = 0ull, skB = 0ull;
        #pragma unroll
        for (int j = 0; j < 8; j++) {
            sqA = fadd2(sqA, *(const ull*)&eqs[pl][p][cb + 2*j]);
            skA = fadd2(skA, *(const ull*)&eks[pl][p][cb + 2*j]);
            sqB = fadd2(sqB, *(const ull*)&eqs[pl][p][cb + 16 + 2*j]);
            skB = fadd2(skB, *(const ull*)&eks[pl][p][cb + 16 + 2*j]);
        }
        float stq, stk;
        unpack2(fadd2(sqA, sqB), stq, hi_); stq += hi_;
        unpack2(fadd2(skA, skB), stk, hi_); stk += hi_;
        stq += __shfl_xor_sync(0xffffffffu, stq, 1);
        stk += __shfl_xor_sync(0xffffffffu, stk, 1);
        float invq = __fdividef(1.f, stq);
        float invk = __fdividef(1.f, stk);
        ull invq2  = pack2(invq, invq);
        ull invk2  = pack2(invk, invk);
        ull ninvk2 = pack2(-invk, -invk);

        ull t01 = 0ull, t23 = 0ull;
        #pragma unroll
        for (int i = 0; i < 8; i++) {
            t01 = fadd2(t01, *(const ull*)&pbp[pl][p][i][0]);
            t23 = fadd2(t23, *(const ull*)&pbp[pl][p][i][2]);
        }
        float pb0, pb1, pb2, pb3;
        unpack2(t01, pb0, pb1);
        unpack2(t23, pb2, pb3);
        float be0 = __fdividef(1.f, 1.f + __expf(-pb0));
        float be1 = __fdividef(1.f, 1.f + __expf(-pb1));
        float be2 = __fdividef(1.f, 1.f + __expf(-pb2));
        float be3 = __fdividef(1.f, 1.f + __expf(-pb3));

        ull dyA = 0ull, dyB = 0ull, dqA = 0ull, dqB = 0ull, dkA = 0ull, dkB = 0ull;
        #pragma unroll
        for (int j = 0; j < 8; j++) {
            ull eqa = *(const ull*)&eqs[pl][p][cb + 2*j];
            ull eqb = *(const ull*)&eqs[pl][p][cb + 16 + 2*j];
            ull eka = *(const ull*)&eks[pl][p][cb + 2*j];
            ull ekb = *(const ull*)&eks[pl][p][cb + 16 + 2*j];
            ull mka = ffma2(eka, ninvk2, fmul2(eqa, invq2));
            ull mkb = ffma2(ekb, ninvk2, fmul2(eqb, invq2));
            dyA = ffma2(wy2[j], mka, dyA);  dyB = ffma2(wy2[j+8], mkb, dyB);
            dqA = ffma2(wq2[j], mka, dqA);  dqB = ffma2(wq2[j+8], mkb, dqB);
            dkA = ffma2(wk2[j], mka, dkA);  dkB = ffma2(wk2[j+8], mkb, dkB);
        }
        ull dy2 = fadd2(dyA, dyB), dq2 = fadd2(dqA, dqB), dk2 = fadd2(dkA, dkB);
        float dy, dq, dk;
        unpack2(dy2, dy, hi_); dy += hi_;
        unpack2(dq2, dq, hi_); dq += hi_;
        unpack2(dk2, dk, hi_); dk += hi_;
        dy += __shfl_xor_sync(0xffffffffu, dy, 1);
        dq += __shfl_xor_sync(0xffffffffu, dq, 1);
        dk += __shfl_xor_sync(0xffffffffu, dk, 1);

        float a0 = be0 * dy, a1 = be1 * dq, a2 = be2 * dk;
        ull a02 = pack2(a0, a0), a12 = pack2(a1, a1), a22 = pack2(a2, a2);
        #pragma unroll
        for (int j = 0; j < 8; j++) {
            ull kva = fmul2(*(const ull*)&eks[pl][p][cb + 2*j],      invk2);
            ull kvb = fmul2(*(const ull*)&eks[pl][p][cb + 16 + 2*j], invk2);
            wy2[j] = ffma2(a02, kva, wy2[j]);   wy2[j+8] = ffma2(a02, kvb, wy2[j+8]);
            wq2[j] = ffma2(a12, kva, wq2[j]);   wq2[j+8] = ffma2(a12, kvb, wq2[j+8]);
            wk2[j] = ffma2(a22, kva, wk2[j]);   wk2[j+8] = ffma2(a22, kvb, wk2[j+8]);
        }
        {
            float ql = eqs[pl][p][lane]      * invq - eks[pl][p][lane]      * invk;
            float qh = eqs[pl][p][lane + 32] * invq - eks[pl][p][lane + 32] * invk;
            float pd = fmaf(wbl, ql, wbh * qh);
            pd = warp_sum(pd);
            float kvl = eks[pl][p][lane] * invk, kvh = eks[pl][p][lane + 32] * invk;
            wbl = fmaf(be3 * kvl, pd, wbl);
            wbh = fmaf(be3 * kvh, pd, wbh);
        }
        // no trailing barrier: next phase A reads xs[pl][pn] (covered by
        // the barrier above) and writes only smem bank pn of this pair.
    }
}

// ============================================================
// Kernel 2: out = LN(h) + ys @ out_w^T via bf16-split tensor cores.
// C = Ahi*Bhi + Ahi*Blo + Alo*Bhi, fp32 accum (mma.m16n8k16.bf16).
// Double-buffered dynamic smem (80KB), ONE barrier per k-tile:
// stores -> bar -> prefetch LDG (overlaps compute) -> compute.
// CTA 128x128, K-step 32, 8 warps of 32x64; rows padded to 80B.
// ============================================================
#define GEMM_SMEM_BYTES (8 * 128 * 40 * 2)   /* 81920 */

__global__ __launch_bounds__(256, 1) void out_gemm_ln_kernel(
    const float* __restrict__ h,
    const float* __restrict__ gamma, const float* __restrict__ lbeta,
    float* __restrict__ out)
{
    extern __shared__ __align__(16) unsigned short smem_g[];
    // layout: [Ahi|Alo|Bhi|Blo], each 2 buffers x 5120 ushorts
    unsigned short* sAhi = smem_g;
    unsigned short* sAlo = smem_g + 2 * 5120;
    unsigned short* sBhi = smem_g + 4 * 5120;
    unsigned short* sBlo = smem_g + 6 * 5120;

    const int tid  = threadIdx.x;
    const int warp = tid >> 5, lane = tid & 31;
    const int wm = (warp >> 1) * 32, wn = (warp & 1) * 64;
    const int m0 = blockIdx.y * 128, n0 = blockIdx.x * 128;

    // staging: thread -> row (0..127), k half (0 or 16)
    const int srow = tid >> 1, skg = (tid & 1) * 16;

    float acc[2][8][4];
    #pragma unroll
    for (int i = 0; i < 2; i++)
        #pragma unroll
        for (int j = 0; j < 8; j++)
            #pragma unroll
            for (int k = 0; k < 4; k++) acc[i][j][k] = 0.f;

    const unsigned short* Ah = g_ys_hi + (size_t)(m0 + srow) * IND + skg;
    const unsigned short* Al = g_ys_lo + (size_t)(m0 + srow) * IND + skg;
    const unsigned short* Bh = g_whi   + (size_t)(n0 + srow) * IND + skg;
    const unsigned short* Bl = g_wlo   + (size_t)(n0 + srow) * IND + skg;

    uint4 vah0 = *(const uint4*)(Ah),     vah1 = *(const uint4*)(Ah + 8);
    uint4 val0 = *(const uint4*)(Al),     val1 = *(const uint4*)(Al + 8);
    uint4 vbh0 = *(const uint4*)(Bh),     vbh1 = *(const uint4*)(Bh + 8);
    uint4 vbl0 = *(const uint4*)(Bl),     vbl1 = *(const uint4*)(Bl + 8);

    const int lr = lane & 15, lc = lane >> 4;
    const uint32 aHiB = smaddr(sAhi), aLoB = smaddr(sAlo);
    const uint32 bHiB = smaddr(sBhi), bLoB = smaddr(sBlo);
    const int sts = srow * 40 + skg;

    for (int kt = 0; kt < IND / 32; ++kt) {
        const int bofs = (kt & 1) * 5120;             // ushort offset
        *(uint4*)(sAhi + bofs + sts) = vah0;  *(uint4*)(sAhi + bofs + sts + 8) = vah1;
        *(uint4*)(sAlo + bofs + sts) = val0;  *(uint4*)(sAlo + bofs + sts + 8) = val1;
        *(uint4*)(sBhi + bofs + sts) = vbh0;  *(uint4*)(sBhi + bofs + sts + 8) = vbh1;
        *(uint4*)(sBlo + bofs + sts) = vbl0;  *(uint4*)(sBlo + bofs + sts + 8) = vbl1;
        __syncthreads();
        if (kt + 1 < IND / 32) {
            const int o = (kt + 1) * 32;
            vah0 = *(const uint4*)(Ah + o); vah1 = *(const uint4*)(Ah + o + 8);
            val0 = *(const uint4*)(Al + o); val1 = *(const uint4*)(Al + o + 8);
            vbh0 = *(const uint4*)(Bh + o); vbh1 = *(const uint4*)(Bh + o + 8);
            vbl0 = *(const uint4*)(Bl + o); vbl1 = *(const uint4*)(Bl + o + 8);
        }
        const uint32 bb = (uint32)(bofs * 2);         // byte offset of buffer
        #pragma unroll
        for (int ks = 0; ks < 2; ks++) {
            const int kb = ks * 32 + lc * 16;   // byte offset within row
            uint32 aH[2][4], aL[2][4];
            #pragma unroll
            for (int mt = 0; mt < 2; mt++) {
                uint32 off = bb + (uint32)(wm + mt * 16 + lr) * 80u + kb;
                ldmx4(aH[mt], aHiB + off);
                ldmx4(aL[mt], aLoB + off);
            }
            uint32 bH[4][4], bL[4][4];
            #pragma unroll
            for (int nc = 0; nc < 4; nc++) {
                uint32 off = bb + (uint32)(wn + nc * 16 + lr) * 80u + kb;
                ldmx4(bH[nc], bHiB + off);   // [n][k] row-major == col-major kxn
                ldmx4(bL[nc], bLoB + off);
            }
            #pragma unroll
            for (int mt = 0; mt < 2; mt++)
                #pragma unroll
                for (int nc = 0; nc < 4; nc++)
                    #pragma unroll
                    for (int hn = 0; hn < 2; hn++) {
                        float* d = acc[mt][nc * 2 + hn];
                        mma16816(d, aH[mt], bH[nc][hn], bH[nc][hn + 2]);
                        mma16816(d, aH[mt], bL[nc][hn], bL[nc][hn + 2]);
                        mma16816(d, aL[mt], bH[nc][hn], bH[nc][hn + 2]);
                    }
        }
        // next iter stores to the other buffer; reads of that buffer
        // (kt-1 compute) completed before this iteration's barrier.
    }

    // epilogue: out = acc + (h - mu) * rsig * gamma + beta
    const int g = lane >> 2, q = lane & 3;
    #pragma unroll
    for (int mt = 0; mt < 2; mt++) {
        int m1 = m0 + wm + mt * 16 + g;
        int m2 = m1 + 8;
        float mu1 = g_mu[m1], rs1 = g_rs[m1];
        float mu2 = g_mu[m2], rs2 = g_rs[m2];
        const float* h1 = h + (size_t)m1 * IND;
        const float* h2 = h + (size_t)m2 * IND;
        float* o1 = out + (size_t)m1 * IND;
        float* o2 = out + (size_t)m2 * IND;
        #pragma unroll
        for (int nt = 0; nt < 8; nt++) {
            int n = n0 + wn + (nt >> 1) * 16 + (nt & 1) * 8 + q * 2;
            float2 gm = *(const float2*)(gamma + n);
            float2 bt = *(const float2*)(lbeta + n);
            float2 hv1 = *(const float2*)(h1 + n);
            float2 hv2 = *(const float2*)(h2 + n);
            const float* d = acc[mt][nt];
            float2 r1, r2;
            r1.x = d[0] + (hv1.x - mu1) * rs1 * gm.x + bt.x;
            r1.y = d[1] + (hv1.y - mu1) * rs1 * gm.y + bt.y;
            r2.x = d[2] + (hv2.x - mu2) * rs2 * gm.x + bt.x;
            r2.y = d[3] + (hv2.y - mu2) * rs2 * gm.y + bt.y;
            *(float2*)(o1 + n) = r1;
            *(float2*)(o2 + n) = r2;
        }
    }
}

// ============================================================
extern "C" void kernel_launch(void* const* d_in, const int* in_sizes, int n_in,
                              void* d_out, int out_size) {
    const float* h   = (const float*)d_in[0];
    const float* Wy  = (const float*)d_in[1];
    const float* Wq  = (const float*)d_in[2];
    const float* Wk  = (const float*)d_in[3];
    const float* wb  = (const float*)d_in[4];
    const float* ow  = (const float*)d_in[5];
    const float* gam = (const float*)d_in[6];
    const float* bet = (const float*)d_in[7];
    float* out = (float*)d_out;

    cudaFuncSetAttribute(out_gemm_ln_kernel,
                         cudaFuncAttributeMaxDynamicSharedMemorySize,
                         GEMM_SMEM_BYTES);

    wconv_kernel<<<IND * IND / 1024, 256>>>(ow);
    srwm_scan_kernel<<<BSZ * NH / 2, 256>>>(h, Wy, Wq, Wk, wb);
    out_gemm_ln_kernel<<<dim3(IND / 128, ROWS / 128), 256, GEMM_SMEM_BYTES>>>(h, gam, bet, out);
}

// round 10
// speedup vs baseline: 1.3309x; 1.3309x over previous
#include <cuda_runtime.h>
#include <cuda_bf16.h>

#define SLEN 256
#define BSZ 8
#define NH 16
#define DH 64
#define IND 1024
#define ROWS (SLEN*BSZ) /* 2048 */

typedef unsigned long long ull;
typedef unsigned int uint32;

// ---- scratch (no allocs allowed -> device globals) ----
__device__ unsigned short g_ys_hi[ROWS * IND];  // scan outputs, bf16 hi (4MB)
__device__ unsigned short g_ys_lo[ROWS * IND];  // bf16 lo of residual (4MB)
__device__ unsigned short g_whi[IND * IND];     // out_w bf16 hi (2MB)
__device__ unsigned short g_wlo[IND * IND];     // out_w bf16 lo (2MB)
__device__ float g_mu[ROWS];
__device__ float g_rs[ROWS];

// ---- f32x2 helpers (sm_103a packed fp32 math, PTX-only) ----
__device__ __forceinline__ ull pack2(float lo, float hi) {
    ull r;
    asm("mov.b64 %0, {%1,%2};" : "=l"(r) : "f"(lo), "f"(hi));
    return r;
}
__device__ __forceinline__ void unpack2(ull v, float& lo, float& hi) {
    asm("mov.b64 {%0,%1}, %2;" : "=f"(lo), "=f"(hi) : "l"(v));
}
__device__ __forceinline__ ull ffma2(ull a, ull b, ull c) {
    ull d;
    asm("fma.rn.f32x2 %0, %1, %2, %3;" : "=l"(d) : "l"(a), "l"(b), "l"(c));
    return d;
}
__device__ __forceinline__ ull fmul2(ull a, ull b) {
    ull d;
    asm("mul.rn.f32x2 %0, %1, %2;" : "=l"(d) : "l"(a), "l"(b));
    return d;
}
__device__ __forceinline__ ull fadd2(ull a, ull b) {
    ull d;
    asm("add.rn.f32x2 %0, %1, %2;" : "=l"(d) : "l"(a), "l"(b));
    return d;
}
__device__ __forceinline__ float warp_sum(float v) {
    #pragma unroll
    for (int o = 16; o; o >>= 1) v += __shfl_xor_sync(0xffffffffu, v, o);
    return v;
}
// bf16 hi/lo split
__device__ __forceinline__ void split_bf16(float v, unsigned short& hi, unsigned short& lo) {
    __nv_bfloat16 hb = __float2bfloat16_rn(v);
    float rem = v - __bfloat162float(hb);
    hi = __bfloat16_as_ushort(hb);
    lo = __bfloat16_as_ushort(__float2bfloat16_rn(rem));
}
// tensor-core primitives
__device__ __forceinline__ uint32 smaddr(const void* p) {
    return (uint32)__cvta_generic_to_shared(p);
}
__device__ __forceinline__ void ldmx4(uint32* r, uint32 a) {
    asm volatile("ldmatrix.sync.aligned.m8n8.x4.shared.b16 {%0,%1,%2,%3},[%4];"
                 : "=r"(r[0]), "=r"(r[1]), "=r"(r[2]), "=r"(r[3]) : "r"(a));
}
__device__ __forceinline__ void mma16816(float* d, const uint32* a, uint32 b0, uint32 b1) {
    asm volatile(
        "mma.sync.aligned.m16n8k16.row.col.f32.bf16.bf16.f32 "
        "{%0,%1,%2,%3},{%4,%5,%6,%7},{%8,%9},{%0,%1,%2,%3};"
        : "+f"(d[0]), "+f"(d[1]), "+f"(d[2]), "+f"(d[3])
        : "r"(a[0]), "r"(a[1]), "r"(a[2]), "r"(a[3]), "r"(b0), "r"(b1));
}

// ============================================================
// Kernel 0: split out_w into bf16 hi/lo
// ============================================================
__global__ __launch_bounds__(256) void wconv_kernel(const float* __restrict__ W) {
    int idx = (blockIdx.x * 256 + threadIdx.x) * 4;
    float4 v = *(const float4*)(W + idx);
    unsigned short h0, l0, h1, l1, h2, l2, h3, l3;
    split_bf16(v.x, h0, l0); split_bf16(v.y, h1, l1);
    split_bf16(v.z, h2, l2); split_bf16(v.w, h3, l3);
    uint2 hv, lv;
    hv.x = (uint32)h0 | ((uint32)h1 << 16); hv.y = (uint32)h2 | ((uint32)h3 << 16);
    lv.x = (uint32)l0 | ((uint32)l1 << 16); lv.y = (uint32)l2 | ((uint32)l3 << 16);
    *(uint2*)(g_whi + idx) = hv;
    *(uint2*)(g_wlo + idx) = lv;
}

// ============================================================
// Kernel 1: LN row stats (fused prologue) + SRWM sequential scan.
// R8 structure (128 CTAs x 128 threads, one __syncthreads/step);
// NEW: phase B reads each eq/ek numerator from smem exactly ONCE
// (register-cached), merging the softmax-total, dv, and rank-1
// update loops -> LDS per thread per step drops 80 -> 32.
// ============================================================
__global__ __launch_bounds__(128, 1) void srwm_scan_kernel(
    const float* __restrict__ h,
    const float* __restrict__ Wy0, const float* __restrict__ Wq0,
    const float* __restrict__ Wk0, const float* __restrict__ wb0)
{
    const int pair = blockIdx.x;          // 0..127
    const int b  = pair >> 4;
    const int hd = pair & 15;
    const int tid  = threadIdx.x;
    const int r    = tid >> 1;            // row 0..63
    const int hf   = tid & 1;             // column half
    const int cb   = hf * 32;             // column base
    const int lane = tid & 31;
    const int warp = tid >> 5;            // 0..3

    // ---------- fused LayerNorm stats: 16 rows per CTA ----------
    {
        #pragma unroll
        for (int rr = 0; rr < 4; rr++) {
            int row = pair * 16 + warp * 4 + rr;
            const float* p = h + (size_t)row * IND + lane * 4;
            float s = 0.f, s2 = 0.f;
            #pragma unroll
            for (int i = 0; i < 8; i++) {
                float4 v = *(const float4*)(p + i * 128);
                s += (v.x + v.y) + (v.z + v.w);
                s2 = fmaf(v.x, v.x, s2); s2 = fmaf(v.y, v.y, s2);
                s2 = fmaf(v.z, v.z, s2); s2 = fmaf(v.w, v.w, s2);
            }
            s  = warp_sum(s);
            s2 = warp_sum(s2);
            if (lane == 0) {
                float mu  = s * (1.f / IND);
                float var = s2 * (1.f / IND) - mu * mu;
                g_mu[row] = mu;
                g_rs[row] = rsqrtf(var + 1e-5f);
            }
        }
    }

    __shared__ __align__(16) float xs[2][64];
    __shared__ __align__(16) float eqs[2][64], eks[2][64];
    __shared__ __align__(16) float pbp[2][8][4];   // beta partials [i][c]

    // register-resident fast weights as packed f32x2 pairs (16 each)
    ull wy2[16], wq2[16], wk2[16];
    {
        const int base = hd * 4096 + r * 64 + cb;   // 16B-aligned
        const ulonglong2* py = (const ulonglong2*)(Wy0 + base);
        const ulonglong2* pq = (const ulonglong2*)(Wq0 + base);
        const ulonglong2* pk = (const ulonglong2*)(Wk0 + base);
        #pragma unroll
        for (int j = 0; j < 8; j++) {
            ulonglong2 vy = py[j]; wy2[2*j] = vy.x; wy2[2*j+1] = vy.y;
            ulonglong2 vq = pq[j]; wq2[2*j] = vq.x; wq2[2*j+1] = vq.y;
            ulonglong2 vk = pk[j]; wk2[2*j] = vk.x; wk2[2*j+1] = vk.y;
        }
    }
    // wb: global layout (hd, j=64, c=4). Warp c owns column c.
    float wbl = wb0[hd * 256 + lane * 4 + warp];
    float wbh = wb0[hd * 256 + (lane + 32) * 4 + warp];

    const float*    hp  = h       + (size_t)b * IND + hd * 64;
    unsigned short* yhp = g_ys_hi + (size_t)b * IND + hd * 64;
    unsigned short* ylp = g_ys_lo + (size_t)b * IND + hd * 64;
    const int stride = BSZ * IND;

    // preload x[0]; prefetch x[1] into regs
    if (tid < 64) xs[0][tid] = hp[tid];
    float nx = (tid < 64) ? __ldg(hp + stride + tid) : 0.f;
    __syncthreads();

    for (int t = 0; t < SLEN; ++t) {
        const int p  = t & 1;
        const int pn = p ^ 1;

        // ================= Phase A (reads xs[p]) =================
        ull ayA = 0ull, ayB = 0ull, aqA = 0ull, aqB = 0ull, akA = 0ull, akB = 0ull;
        #pragma unroll
        for (int j = 0; j < 8; j++) {
            ull x2a = *(const ull*)&xs[p][cb + 2*j];
            ull x2b = *(const ull*)&xs[p][cb + 16 + 2*j];
            ayA = ffma2(wy2[j], x2a, ayA);  ayB = ffma2(wy2[j+8], x2b, ayB);
            aqA = ffma2(wq2[j], x2a, aqA);  aqB = ffma2(wq2[j+8], x2b, aqB);
            akA = ffma2(wk2[j], x2a, akA);  akB = ffma2(wk2[j+8], x2b, akB);
        }
        ull ay = fadd2(ayA, ayB), aq = fadd2(aqA, aqB), ak = fadd2(akA, akB);
        float zy, zq, zk, hi_;
        unpack2(ay, zy, hi_); zy += hi_;
        unpack2(aq, zq, hi_); zq += hi_;
        unpack2(ak, zk, hi_); zk += hi_;
        zy += __shfl_xor_sync(0xffffffffu, zy, 1);
        zq += __shfl_xor_sync(0xffffffffu, zq, 1);
        zk += __shfl_xor_sync(0xffffffffu, zk, 1);

        float eq = __expf(zq), ek = __expf(zk);
        if (hf == 0) {
            eqs[p][r] = eq; eks[p][r] = ek;
            unsigned short yh, yl;
            split_bf16(zy, yh, yl);
            yhp[(size_t)t * stride + r] = yh;     // y output (pre-update Wy)
            ylp[(size_t)t * stride + r] = yl;
        }
        // beta partial: 2 shfl levels; lanes 0..7 hold 8 partials
        {
            float pb = fmaf(wbl, xs[p][lane], wbh * xs[p][lane + 32]);
            pb += __shfl_xor_sync(0xffffffffu, pb, 16);
            pb += __shfl_xor_sync(0xffffffffu, pb, 8);
            if (lane < 8) pbp[p][lane][warp] = pb;
        }
        if (tid < 64 && t + 1 < SLEN) xs[pn][tid] = nx;   // publish x[t+1]
        __syncthreads();   // single barrier per step

        // ============ Phase B (reads bank p ONCE, writes regs only) ============
        if (tid < 64 && t + 2 < SLEN) nx = __ldg(hp + (size_t)(t + 2) * stride + tid);

        // single pass: load all 32 numerator pairs into regs, sum on the fly
        ull eq2[16], ek2[16];
        ull sq2 = 0ull, sk2 = 0ull;
        #pragma unroll
        for (int j = 0; j < 8; j++) {
            eq2[j]   = *(const ull*)&eqs[p][cb + 2*j];
            ek2[j]   = *(const ull*)&eks[p][cb + 2*j];
            eq2[j+8] = *(const ull*)&eqs[p][cb + 16 + 2*j];
            ek2[j+8] = *(const ull*)&eks[p][cb + 16 + 2*j];
            sq2 = fadd2(sq2, fadd2(eq2[j], eq2[j+8]));
            sk2 = fadd2(sk2, fadd2(ek2[j], ek2[j+8]));
        }
        float stq, stk;
        unpack2(sq2, stq, hi_); stq += hi_;
        unpack2(sk2, stk, hi_); stk += hi_;
        stq += __shfl_xor_sync(0xffffffffu, stq, 1);
        stk += __shfl_xor_sync(0xffffffffu, stk, 1);
        float invq = __fdividef(1.f, stq);
        float invk = __fdividef(1.f, stk);
        ull invq2  = pack2(invq, invq);
        ull invk2  = pack2(invk, invk);
        ull ninvk2 = pack2(-invk, -invk);

        // betas from phase-A partials (packed fadd2 trees)
        ull t01 = 0ull, t23 = 0ull;
        #pragma unroll
        for (int i = 0; i < 8; i++) {
            t01 = fadd2(t01, *(const ull*)&pbp[p][i][0]);
            t23 = fadd2(t23, *(const ull*)&pbp[p][i][2]);
        }
        float pb0, pb1, pb2, pb3;
        unpack2(t01, pb0, pb1);
        unpack2(t23, pb2, pb3);
        float be0 = __fdividef(1.f, 1.f + __expf(-pb0));
        float be1 = __fdividef(1.f, 1.f + __expf(-pb1));
        float be2 = __fdividef(1.f, 1.f + __expf(-pb2));
        float be3 = __fdividef(1.f, 1.f + __expf(-pb3));

        // dv = W (q - k) from cached numerators (no LDS)
        ull dyA = 0ull, dyB = 0ull, dqA = 0ull, dqB = 0ull, dkA = 0ull, dkB = 0ull;
        #pragma unroll
        for (int j = 0; j < 8; j++) {
            ull mka = ffma2(ek2[j],   ninvk2, fmul2(eq2[j],   invq2));
            ull mkb = ffma2(ek2[j+8], ninvk2, fmul2(eq2[j+8], invq2));
            dyA = ffma2(wy2[j], mka, dyA);  dyB = ffma2(wy2[j+8], mkb, dyB);
            dqA = ffma2(wq2[j], mka, dqA);  dqB = ffma2(wq2[j+8], mkb, dqB);
            dkA = ffma2(wk2[j], mka, dkA);  dkB = ffma2(wk2[j+8], mkb, dkB);
        }
        ull dy2 = fadd2(dyA, dyB), dq2 = fadd2(dqA, dqB), dk2 = fadd2(dkA, dkB);
        float dy, dq, dk;
        unpack2(dy2, dy, hi_); dy += hi_;
        unpack2(dq2, dq, hi_); dq += hi_;
        unpack2(dk2, dk, hi_); dk += hi_;
        dy += __shfl_xor_sync(0xffffffffu, dy, 1);
        dq += __shfl_xor_sync(0xffffffffu, dq, 1);
        dk += __shfl_xor_sync(0xffffffffu, dk, 1);

        // rank-1 updates from cached ek2 (no LDS)
        float a0 = be0 * dy, a1 = be1 * dq, a2 = be2 * dk;
        ull a02 = pack2(a0, a0), a12 = pack2(a1, a1), a22 = pack2(a2, a2);
        #pragma unroll
        for (int j = 0; j < 16; j++) {
            ull kv2 = fmul2(ek2[j], invk2);
            wy2[j] = ffma2(a02, kv2, wy2[j]);
            wq2[j] = ffma2(a12, kv2, wq2[j]);
            wk2[j] = ffma2(a22, kv2, wk2[j]);
        }
        // wb update: warp c computes dvb_c, updates its private column
        {
            float ql = eqs[p][lane]      * invq - eks[p][lane]      * invk;
            float qh = eqs[p][lane + 32] * invq - eks[p][lane + 32] * invk;
            float pd = fmaf(wbl, ql, wbh * qh);
            pd = warp_sum(pd);
            float kvl = eks[p][lane] * invk, kvh = eks[p][lane + 32] * invk;
            wbl = fmaf(be3 * kvl, pd, wbl);
            wbh = fmaf(be3 * kvh, pd, wbh);
        }
        // no trailing barrier: next phase A reads xs[pn] (covered by the
        // barrier above) and writes only smem bank pn.
    }
}

// ============================================================
// Kernel 2: out = LN(h) + ys @ out_w^T via bf16-split tensor cores.
// (exact R8 version: static smem, 2 barriers/kt, 71us known-good)
// C = Ahi*Bhi + Ahi*Blo + Alo*Bhi, fp32 accum (mma.m16n8k16.bf16).
// B tile is [n][k] row-major = col-major kxn -> plain ldmatrix.
// CTA 128x128, K-step 32, 8 warps of 32x64; rows padded to 80B.
// ============================================================
__global__ __launch_bounds__(256, 1) void out_gemm_ln_kernel(
    const float* __restrict__ h,
    const float* __restrict__ gamma, const float* __restrict__ lbeta,
    float* __restrict__ out)
{
    __shared__ __align__(16) unsigned short sAhi[128 * 40], sAlo[128 * 40];
    __shared__ __align__(16) unsigned short sBhi[128 * 40], sBlo[128 * 40];

    const int tid  = threadIdx.x;
    const int warp = tid >> 5, lane = tid & 31;
    const int wm = (warp >> 1) * 32, wn = (warp & 1) * 64;
    const int m0 = blockIdx.y * 128, n0 = blockIdx.x * 128;

    // staging: thread -> row (0..127), k half (0 or 16)
    const int srow = tid >> 1, skg = (tid & 1) * 16;

    float acc[2][8][4];
    #pragma unroll
    for (int i = 0; i < 2; i++)
        #pragma unroll
        for (int j = 0; j < 8; j++)
            #pragma unroll
            for (int k = 0; k < 4; k++) acc[i][j][k] = 0.f;

    const unsigned short* Ah = g_ys_hi + (size_t)(m0 + srow) * IND + skg;
    const unsigned short* Al = g_ys_lo + (size_t)(m0 + srow) * IND + skg;
    const unsigned short* Bh = g_whi   + (size_t)(n0 + srow) * IND + skg;
    const unsigned short* Bl = g_wlo   + (size_t)(n0 + srow) * IND + skg;

    uint4 vah0 = *(const uint4*)(Ah),     vah1 = *(const uint4*)(Ah + 8);
    uint4 val0 = *(const uint4*)(Al),     val1 = *(const uint4*)(Al + 8);
    uint4 vbh0 = *(const uint4*)(Bh),     vbh1 = *(const uint4*)(Bh + 8);
    uint4 vbl0 = *(const uint4*)(Bl),     vbl1 = *(const uint4*)(Bl + 8);

    const int lr = lane & 15, lc = lane >> 4;
    const uint32 aHiB = smaddr(sAhi), aLoB = smaddr(sAlo);
    const uint32 bHiB = smaddr(sBhi), bLoB = smaddr(sBlo);
    const int sts = srow * 40 + skg;

    for (int kt = 0; kt < IND / 32; ++kt) {
        __syncthreads();   // previous tile fully consumed
        *(uint4*)(sAhi + sts) = vah0;  *(uint4*)(sAhi + sts + 8) = vah1;
        *(uint4*)(sAlo + sts) = val0;  *(uint4*)(sAlo + sts + 8) = val1;
        *(uint4*)(sBhi + sts) = vbh0;  *(uint4*)(sBhi + sts + 8) = vbh1;
        *(uint4*)(sBlo + sts) = vbl0;  *(uint4*)(sBlo + sts + 8) = vbl1;
        __syncthreads();
        if (kt + 1 < IND / 32) {
            const int o = (kt + 1) * 32;
            vah0 = *(const uint4*)(Ah + o); vah1 = *(const uint4*)(Ah + o + 8);
            val0 = *(const uint4*)(Al + o); val1 = *(const uint4*)(Al + o + 8);
            vbh0 = *(const uint4*)(Bh + o); vbh1 = *(const uint4*)(Bh + o + 8);
            vbl0 = *(const uint4*)(Bl + o); vbl1 = *(const uint4*)(Bl + o + 8);
        }
        #pragma unroll
        for (int ks = 0; ks < 2; ks++) {
            const int kb = ks * 32 + lc * 16;   // byte offset within row
            uint32 aH[2][4], aL[2][4];
            #pragma unroll
            for (int mt = 0; mt < 2; mt++) {
                uint32 off = (uint32)(wm + mt * 16 + lr) * 80u + kb;
                ldmx4(aH[mt], aHiB + off);
                ldmx4(aL[mt], aLoB + off);
            }
            uint32 bH[4][4], bL[4][4];
            #pragma unroll
            for (int nc = 0; nc < 4; nc++) {
                uint32 off = (uint32)(wn + nc * 16 + lr) * 80u + kb;
                ldmx4(bH[nc], bHiB + off);   // [n][k] row-major == col-major kxn
                ldmx4(bL[nc], bLoB + off);
            }
            #pragma unroll
            for (int mt = 0; mt < 2; mt++)
                #pragma unroll
                for (int nc = 0; nc < 4; nc++)
                    #pragma unroll
                    for (int hn = 0; hn < 2; hn++) {
                        float* d = acc[mt][nc * 2 + hn];
                        mma16816(d, aH[mt], bH[nc][hn], bH[nc][hn + 2]);
                        mma16816(d, aH[mt], bL[nc][hn], bL[nc][hn + 2]);
                        mma16816(d, aL[mt], bH[nc][hn], bH[nc][hn + 2]);
                    }
        }
    }

    // epilogue: out = acc + (h - mu) * rsig * gamma + beta
    const int g = lane >> 2, q = lane & 3;
    #pragma unroll
    for (int mt = 0; mt < 2; mt++) {
        int m1 = m0 + wm + mt * 16 + g;
        int m2 = m1 + 8;
        float mu1 = g_mu[m1], rs1 = g_rs[m1];
        float mu2 = g_mu[m2], rs2 = g_rs[m2];
        const float* h1 = h + (size_t)m1 * IND;
        const float* h2 = h + (size_t)m2 * IND;
        float* o1 = out + (size_t)m1 * IND;
        float* o2 = out + (size_t)m2 * IND;
        #pragma unroll
        for (int nt = 0; nt < 8; nt++) {
            int n = n0 + wn + (nt >> 1) * 16 + (nt & 1) * 8 + q * 2;
            float2 gm = *(const float2*)(gamma + n);
            float2 bt = *(const float2*)(lbeta + n);
            float2 hv1 = *(const float2*)(h1 + n);
            float2 hv2 = *(const float2*)(h2 + n);
            const float* d = acc[mt][nt];
            float2 r1, r2;
            r1.x = d[0] + (hv1.x - mu1) * rs1 * gm.x + bt.x;
            r1.y = d[1] + (hv1.y - mu1) * rs1 * gm.y + bt.y;
            r2.x = d[2] + (hv2.x - mu2) * rs2 * gm.x + bt.x;
            r2.y = d[3] + (hv2.y - mu2) * rs2 * gm.y + bt.y;
            *(float2*)(o1 + n) = r1;
            *(float2*)(o2 + n) = r2;
        }
    }
}

// ============================================================
extern "C" void kernel_launch(void* const* d_in, const int* in_sizes, int n_in,
                              void* d_out, int out_size) {
    const float* h   = (const float*)d_in[0];
    const float* Wy  = (const float*)d_in[1];
    const float* Wq  = (const float*)d_in[2];
    const float* Wk  = (const float*)d_in[3];
    const float* wb  = (const float*)d_in[4];
    const float* ow  = (const float*)d_in[5];
    const float* gam = (const float*)d_in[6];
    const float* bet = (const float*)d_in[7];
    float* out = (float*)d_out;

    wconv_kernel<<<IND * IND / 1024, 256>>>(ow);
    srwm_scan_kernel<<<BSZ * NH, 128>>>(h, Wy, Wq, Wk, wb);
    out_gemm_ln_kernel<<<dim3(IND / 128, ROWS / 128), 256>>>(h, gam, bet, out);
}